// round 4
// baseline (speedup 1.0000x reference)
#include <cuda_runtime.h>
#include <cuda_bf16.h>
#include <cstdint>

// Single-row fold (same tables as R3):
//   A[r] = W[r]   + W[131] + W[138]    rows   0..64   (same chain, dres!=0)
//   B[t] = W[32]  + W[66+t]+ W[138]    rows  65..129  (same chain, dres==0)
//   C[c] = W[65]  + W[131] + W[133+c]  rows 130..134  (diff chain)
//   row 135 = W[132] (entity row)
// Data is random ints [0,64): ~98.4% of pairs are diff-chain, and ~95% of those
// clamp to row 130 or 134 -> keep those two rows + entity row in registers and
// only touch smem for the rare middle cases.

#define TAB_ROWS 136

__global__ void __launch_bounds__(512, 3)
rpe_kernel(const float* __restrict__ feats, const float* __restrict__ W,
           float* __restrict__ out, int n)
{
    extern __shared__ float smem[];
    float* S   = smem;                            // TAB_ROWS*128 floats
    int*  jidx = (int*)(smem + TAB_ROWS * 128);   // n ints

    const int tid = threadIdx.x;
    const int i   = blockIdx.x;

    // ---- Phase 0: build folded single-row table ----
    for (int idx = tid; idx < TAB_ROWS * 128; idx += blockDim.x) {
        int r = idx >> 7;
        int e = idx & 127;
        float v;
        if (r < 65) {
            v = W[r * 128 + e] + W[131 * 128 + e] + W[138 * 128 + e];
        } else if (r < 130) {
            v = W[32 * 128 + e] + W[(66 + (r - 65)) * 128 + e] + W[138 * 128 + e];
        } else if (r < 135) {
            v = W[65 * 128 + e] + W[131 * 128 + e] + W[(133 + (r - 130)) * 128 + e];
        } else {
            v = W[132 * 128 + e];
        }
        S[idx] = v;
    }

    // ---- Phase 0b: per-j packed index (row | ent<<8) ----
    const float res_i  = feats[i * 10 + 0];
    const float tok_i  = feats[i * 10 + 1];
    const float asym_i = feats[i * 10 + 2];
    const float ent_i  = feats[i * 10 + 3];
    const float sym_i  = feats[i * 10 + 4];

    for (int j = tid; j < n; j += blockDim.x) {
        const float res_j  = feats[j * 10 + 0];
        const float tok_j  = feats[j * 10 + 1];
        const float asym_j = feats[j * 10 + 2];
        const float ent_j  = feats[j * 10 + 3];
        const float sym_j  = feats[j * 10 + 4];

        int row;
        if (asym_i == asym_j) {
            const int dres = (int)(res_i - res_j);
            if (dres != 0) {
                row = min(max(dres + 32, 0), 64);            // A table
            } else {
                const int dtok = (int)(tok_i - tok_j);
                row = 65 + min(max(dtok + 32, 0), 64);       // B table
            }
        } else {
            row = 130 + min(max((int)(sym_i - sym_j) + 2, 0), 4);  // C table
        }
        const int ent = (ent_i == ent_j) ? 1 : 0;
        jidx[j] = row | (ent << 8);
    }
    __syncthreads();

    // ---- Phase 1: register-cached hot rows + streaming stores ----
    const int e4    = tid & 31;                    // float4 lane within 128-dim row
    const int wid   = tid >> 5;
    const int warps = blockDim.x >> 5;
    const float4* __restrict__ S4 = (const float4*)S;

    const float4 r130 = S4[130 * 32 + e4];         // dominant diff-chain rows
    const float4 r134 = S4[134 * 32 + e4];
    const float4 went = S4[135 * 32 + e4];         // entity row

    float* __restrict__ out_i = out + ((size_t)i * (size_t)n) * 128;

    int j = wid;
    #pragma unroll 1
    for (; j + 3 * warps < n; j += 4 * warps) {
        float4 v[4];
        int    pp[4];
        #pragma unroll
        for (int u = 0; u < 4; u++) {
            const int p   = jidx[j + u * warps];   // LDS broadcast (warp-uniform)
            const int row = p & 255;
            float4 v0;
            if (row == 130)      v0 = r130;        // ~47.7% (warp-uniform branch)
            else if (row == 134) v0 = r134;        // ~47.7%
            else                 v0 = S4[row * 32 + e4];  // ~6% fallback
            pp[u] = p;
            v[u]  = v0;
        }
        #pragma unroll
        for (int u = 0; u < 4; u++) {
            float4 v0 = v[u];
            if (pp[u] >> 8) {                      // entity add, ~1.6%
                v0.x += went.x; v0.y += went.y; v0.z += went.z; v0.w += went.w;
            }
            __stcs((float4*)(out_i + (size_t)(j + u * warps) * 128) + e4, v0);
        }
    }
    for (; j < n; j += warps) {
        const int p   = jidx[j];
        const int row = p & 255;
        float4 v;
        if (row == 130)      v = r130;
        else if (row == 134) v = r134;
        else                 v = S4[row * 32 + e4];
        if (p >> 8) { v.x += went.x; v.y += went.y; v.z += went.z; v.w += went.w; }
        __stcs((float4*)(out_i + (size_t)j * 128) + e4, v);
    }
}

extern "C" void kernel_launch(void* const* d_in, const int* in_sizes, int n_in,
                              void* d_out, int out_size)
{
    const float* feats = (const float*)d_in[0];   // [1, n, 10] f32
    const float* W     = (const float*)d_in[1];   // [139, 128] f32
    float* out         = (float*)d_out;           // [1, n, n, 128] f32

    const int n = in_sizes[0] / 10;               // b == 1

    const int smem_bytes = TAB_ROWS * 128 * (int)sizeof(float) + n * (int)sizeof(int);
    cudaFuncSetAttribute(rpe_kernel, cudaFuncAttributeMaxDynamicSharedMemorySize, smem_bytes);

    rpe_kernel<<<n, 512, smem_bytes>>>(feats, W, out, n);
}

// round 5
// speedup vs baseline: 1.1394x; 1.1394x over previous
#include <cuda_runtime.h>
#include <cuda_bf16.h>
#include <cstdint>

// Folded table in GLOBAL memory (i-independent, built once by a pre-kernel):
//   rows   0..4  : C[c] = W[65] + W[131] + W[133+c]   (diff chain, HOT: ~98.4% of pairs)
//   row    5     : W[132]                             (entity row)
//   rows   6..70 : A[r] = W[r] + W[131] + W[138]      (same chain, dres!=0)
//   rows  71..135: B[t] = W[32] + W[66+t] + W[138]    (same chain, dres==0)
// Main kernel keeps only jidx (4 KB) in smem -> 8 blocks/SM -> grid fits ONE wave.

#define TAB_ROWS 136

__device__ float g_table[TAB_ROWS * 128];

__global__ void build_table(const float* __restrict__ W)
{
    const int idx = blockIdx.x * blockDim.x + threadIdx.x;
    if (idx >= TAB_ROWS * 128) return;
    const int r = idx >> 7;
    const int e = idx & 127;
    float v;
    if (r < 5) {
        v = W[65 * 128 + e] + W[131 * 128 + e] + W[(133 + r) * 128 + e];
    } else if (r == 5) {
        v = W[132 * 128 + e];
    } else if (r < 71) {
        v = W[(r - 6) * 128 + e] + W[131 * 128 + e] + W[138 * 128 + e];
    } else {
        v = W[32 * 128 + e] + W[(66 + (r - 71)) * 128 + e] + W[138 * 128 + e];
    }
    g_table[idx] = v;
}

__global__ void __launch_bounds__(256, 8)
rpe_main(const float* __restrict__ feats, float* __restrict__ out, int n)
{
    __shared__ int jidx[1024];

    const int tid = threadIdx.x;
    const int i   = blockIdx.x;

    // ---- Phase A: per-j packed index (row | ent<<8) ----
    const float res_i  = feats[i * 10 + 0];
    const float tok_i  = feats[i * 10 + 1];
    const float asym_i = feats[i * 10 + 2];
    const float ent_i  = feats[i * 10 + 3];
    const float sym_i  = feats[i * 10 + 4];

    for (int j = tid; j < n; j += blockDim.x) {
        const float res_j  = feats[j * 10 + 0];
        const float tok_j  = feats[j * 10 + 1];
        const float asym_j = feats[j * 10 + 2];
        const float ent_j  = feats[j * 10 + 3];
        const float sym_j  = feats[j * 10 + 4];

        int row;
        if (asym_i == asym_j) {
            const int dres = (int)(res_i - res_j);
            if (dres != 0) {
                row = 6 + min(max(dres + 32, 0), 64);          // A table
            } else {
                const int dtok = (int)(tok_i - tok_j);
                row = 71 + min(max(dtok + 32, 0), 64);         // B table
            }
        } else {
            row = min(max((int)(sym_i - sym_j) + 2, 0), 4);    // C table (hot)
        }
        const int ent = (ent_i == ent_j) ? 1 : 0;
        jidx[j] = row | (ent << 8);
    }
    __syncthreads();

    // ---- Phase B: warp-per-pair gather from L1-resident global table ----
    const int e4    = tid & 31;                  // float4 lane within 128-dim row
    const int wid   = tid >> 5;
    const int warps = blockDim.x >> 5;           // 8
    const float4* __restrict__ T4 = (const float4*)g_table;

    const float4 went = __ldg(&T4[5 * 32 + e4]); // entity row in registers

    float* __restrict__ out_i = out + ((size_t)i * (size_t)n) * 128;

    int j = wid;
    // unroll x2 for load-latency ILP
    for (; j + warps < n; j += 2 * warps) {
        const int j2 = j + warps;
        const int p0 = jidx[j];
        const int p1 = jidx[j2];
        float4 v0 = __ldg(&T4[(p0 & 255) * 32 + e4]);
        float4 v1 = __ldg(&T4[(p1 & 255) * 32 + e4]);
        if (p0 >> 8) { v0.x += went.x; v0.y += went.y; v0.z += went.z; v0.w += went.w; }
        if (p1 >> 8) { v1.x += went.x; v1.y += went.y; v1.z += went.z; v1.w += went.w; }
        __stcs((float4*)(out_i + (size_t)j  * 128) + e4, v0);
        __stcs((float4*)(out_i + (size_t)j2 * 128) + e4, v1);
    }
    for (; j < n; j += warps) {
        const int p = jidx[j];
        float4 v = __ldg(&T4[(p & 255) * 32 + e4]);
        if (p >> 8) { v.x += went.x; v.y += went.y; v.z += went.z; v.w += went.w; }
        __stcs((float4*)(out_i + (size_t)j * 128) + e4, v);
    }
}

extern "C" void kernel_launch(void* const* d_in, const int* in_sizes, int n_in,
                              void* d_out, int out_size)
{
    const float* feats = (const float*)d_in[0];   // [1, n, 10] f32
    const float* W     = (const float*)d_in[1];   // [139, 128] f32
    float* out         = (float*)d_out;           // [1, n, n, 128] f32

    const int n = in_sizes[0] / 10;               // b == 1 (n == 1024)

    build_table<<<(TAB_ROWS * 128 + 255) / 256, 256>>>(W);
    rpe_main<<<n, 256>>>(feats, out, n);
}